// round 2
// baseline (speedup 1.0000x reference)
#include <cuda_runtime.h>
#include <math.h>

#define BATCH 256
#define TLEN  512
#define CIN0  271
#define CH    320
#define NSUBJ 4
#define EPSV  1e-5f

#define TILE_T  128
#define TILE_CO 64
#define KC      8
#define NTH     256

// Scratch (allocation-free rule: __device__ globals)
__device__ float g_bufA[(size_t)BATCH * CH * TLEN];   // 167.8 MB
__device__ float g_bufB[(size_t)BATCH * CH * TLEN];   // 167.8 MB
__device__ float g_wt[3 * CH * CH];                   // transposed weights [tap][ci][co]
__device__ float g_sum[NSUBJ * CH];
__device__ float g_sumsq[NSUBJ * CH];
__device__ float g_scale[NSUBJ * CH];
__device__ float g_shift[NSUBJ * CH];
__device__ int   g_cnt[NSUBJ];

__device__ __forceinline__ float gelu_f(float x) {
    // exact erf GELU (matches jax.nn.gelu approximate=False / torch F.gelu)
    return 0.5f * x * (1.0f + erff(x * 0.7071067811865475f));
}

// ---------------------------------------------------------------------------
// Per-subject batch counts (one block of 256 threads, one thread per batch elem)
// ---------------------------------------------------------------------------
__global__ void count_kernel(const int* __restrict__ subj) {
    __shared__ int c[NSUBJ];
    int tid = threadIdx.x;
    if (tid < NSUBJ) c[tid] = 0;
    __syncthreads();
    atomicAdd(&c[subj[tid]], 1);
    __syncthreads();
    if (tid < NSUBJ) g_cnt[tid] = c[tid];
}

__global__ void zero_stats_kernel() {
    int i = blockIdx.x * blockDim.x + threadIdx.x;
    if (i < NSUBJ * CH) { g_sum[i] = 0.f; g_sumsq[i] = 0.f; }
}

// w: [CH][cin][3] row-major  ->  g_wt: [tap][cin][CH]
__global__ void transpose_w_kernel(const float* __restrict__ w, int cin) {
    int i = blockIdx.x * blockDim.x + threadIdx.x;
    int n = CH * cin * 3;
    if (i >= n) return;
    int tap = i % 3;
    int ci  = (i / 3) % cin;
    int co  = i / (3 * cin);
    g_wt[((size_t)tap * cin + ci) * CH + co] = w[i];
}

// ---------------------------------------------------------------------------
// Conv1d (K=3, SAME) implicit GEMM. One block: 64 co x 128 t for one batch b.
// Optionally adds residual (input at same [co][t]). Accumulates per-subject
// per-channel sum/sumsq of the OUTPUT (pre-BN) via warp reduce + atomics.
// ---------------------------------------------------------------------------
template <int CIN, bool RES>
__global__ void __launch_bounds__(NTH) conv_kernel(
    const float* __restrict__ in,      // [BATCH][CIN][TLEN]
    const float* __restrict__ bias,    // [CH]
    const int*   __restrict__ subj,    // [BATCH]
    float*       __restrict__ out)     // [BATCH][CH][TLEN]
{
    __shared__ float Ws[3][KC][TILE_CO];
    __shared__ float Xs[KC][TILE_T + 2];

    const int b     = blockIdx.z;
    const int coBlk = blockIdx.y * TILE_CO;
    const int tBlk  = blockIdx.x * TILE_T;
    const int tid   = threadIdx.x;
    const int co0   = (tid >> 5) * 8;   // 8 warps -> 8 co-groups of 8
    const int t0    = (tid & 31) * 4;   // 32 lanes -> 128 t positions

    const float* inB = in + (size_t)b * CIN * TLEN;

    float acc[8][4];
#pragma unroll
    for (int r = 0; r < 8; r++)
#pragma unroll
        for (int j = 0; j < 4; j++) acc[r][j] = 0.f;

    for (int c0 = 0; c0 < CIN; c0 += KC) {
        __syncthreads();
        // Weights: g_wt[(tap*CIN + cig)*CH + coBlk + co] — coalesced in co.
#pragma unroll
        for (int i = tid; i < 3 * KC * TILE_CO; i += NTH) {   // 6 iterations
            int co  = i & (TILE_CO - 1);
            int r   = i >> 6;
            int ci  = r & (KC - 1);
            int tap = r >> 3;
            int cig = c0 + ci;
            Ws[tap][ci][co] = (cig < CIN)
                ? g_wt[((size_t)tap * CIN + cig) * CH + coBlk + co] : 0.f;
        }
        // Input tile with halo: Xs[ci][tt] = in[b][cig][tBlk + tt - 1], zero-padded.
        for (int i = tid; i < KC * (TILE_T + 2); i += NTH) {
            int ci = i / (TILE_T + 2);
            int tt = i - ci * (TILE_T + 2);
            int gt = tBlk + tt - 1;
            int cig = c0 + ci;
            float v = 0.f;
            if (cig < CIN && (unsigned)gt < (unsigned)TLEN)
                v = inB[(size_t)cig * TLEN + gt];
            Xs[ci][tt] = v;
        }
        __syncthreads();

#pragma unroll
        for (int ci = 0; ci < KC; ci++) {
            float xv[6];
#pragma unroll
            for (int j = 0; j < 6; j++) xv[j] = Xs[ci][t0 + j];
#pragma unroll
            for (int tap = 0; tap < 3; tap++) {
                float wv[8];
#pragma unroll
                for (int r = 0; r < 8; r++) wv[r] = Ws[tap][ci][co0 + r];
#pragma unroll
                for (int r = 0; r < 8; r++)
#pragma unroll
                    for (int j = 0; j < 4; j++)
                        acc[r][j] = fmaf(wv[r], xv[j + tap], acc[r][j]);
            }
        }
    }

    // Epilogue: bias (+ residual), store, and stats accumulation.
    const int s = subj[b];
    float* outB = out + ((size_t)b * CH + coBlk) * TLEN + tBlk;
    const float* resB = in + ((size_t)b * CH + coBlk) * TLEN + tBlk; // valid only if RES

    float ssum[8], ssq[8];
#pragma unroll
    for (int r = 0; r < 8; r++) {
        float bv = bias[coBlk + co0 + r];
        float4 res4 = make_float4(0.f, 0.f, 0.f, 0.f);
        if (RES)
            res4 = *(const float4*)(resB + (size_t)(co0 + r) * TLEN + t0);
        float v0 = acc[r][0] + bv;
        float v1 = acc[r][1] + bv;
        float v2 = acc[r][2] + bv;
        float v3 = acc[r][3] + bv;
        if (RES) { v0 += res4.x; v1 += res4.y; v2 += res4.z; v3 += res4.w; }
        *(float4*)(outB + (size_t)(co0 + r) * TLEN + t0) = make_float4(v0, v1, v2, v3);
        ssum[r] = v0 + v1 + v2 + v3;
        ssq[r]  = v0 * v0 + v1 * v1 + v2 * v2 + v3 * v3;
    }
    // Warp lanes span t only (same co rows) -> shuffle reduce then 16 atomics/warp.
#pragma unroll
    for (int off = 16; off; off >>= 1) {
#pragma unroll
        for (int r = 0; r < 8; r++) {
            ssum[r] += __shfl_down_sync(0xffffffffu, ssum[r], off);
            ssq[r]  += __shfl_down_sync(0xffffffffu, ssq[r],  off);
        }
    }
    if ((tid & 31) == 0) {
#pragma unroll
        for (int r = 0; r < 8; r++) {
            atomicAdd(&g_sum[s * CH + coBlk + co0 + r],   ssum[r]);
            atomicAdd(&g_sumsq[s * CH + coBlk + co0 + r], ssq[r]);
        }
    }
}

__global__ void finalize_kernel(const float* __restrict__ gamma,
                                const float* __restrict__ beta) {
    int i = blockIdx.x * blockDim.x + threadIdx.x;
    if (i >= NSUBJ * CH) return;
    int s = i / CH;
    float cnt  = fmaxf((float)g_cnt[s] * (float)TLEN, 1.0f);
    float mean = g_sum[i] / cnt;
    float var  = g_sumsq[i] / cnt - mean * mean;
    float sc   = gamma[i] * rsqrtf(var + EPSV);
    g_scale[i] = sc;
    g_shift[i] = beta[i] - mean * sc;
}

// dst[i] = gelu(src[i]*scale + shift), float4-vectorized; src==dst allowed.
__global__ void bn_gelu_kernel(const float* __restrict__ src,
                               float* __restrict__ dst,
                               const int* __restrict__ subj) {
    size_t idx = (size_t)blockIdx.x * blockDim.x + threadIdx.x;
    size_t n4 = (size_t)BATCH * CH * TLEN / 4;
    if (idx >= n4) return;
    size_t e = idx * 4;
    int b = (int)(e / ((size_t)CH * TLEN));
    int c = (int)((e / TLEN) % CH);
    int s = subj[b];
    float sc = g_scale[s * CH + c];
    float sh = g_shift[s * CH + c];
    float4 v = ((const float4*)src)[idx];
    v.x = gelu_f(fmaf(v.x, sc, sh));
    v.y = gelu_f(fmaf(v.y, sc, sh));
    v.z = gelu_f(fmaf(v.z, sc, sh));
    v.w = gelu_f(fmaf(v.w, sc, sh));
    ((float4*)dst)[idx] = v;
}

// ---------------------------------------------------------------------------
extern "C" void kernel_launch(void* const* d_in, const int* in_sizes, int n_in,
                              void* d_out, int out_size) {
    const float* X    = (const float*)d_in[0];
    const int*   subj = (const int*)  d_in[1];
    const float* w0   = (const float*)d_in[2];
    const float* b0   = (const float*)d_in[3];
    const float* w1   = (const float*)d_in[4];
    const float* b1   = (const float*)d_in[5];
    const float* w2   = (const float*)d_in[6];
    const float* b2   = (const float*)d_in[7];
    const float* g0   = (const float*)d_in[8];
    const float* be0  = (const float*)d_in[9];
    const float* g1   = (const float*)d_in[10];
    const float* be1  = (const float*)d_in[11];
    const float* g2   = (const float*)d_in[12];
    const float* be2  = (const float*)d_in[13];
    float* out = (float*)d_out;
    (void)in_sizes; (void)n_in; (void)out_size;

    float *pA, *pB;
    cudaGetSymbolAddress((void**)&pA, g_bufA);
    cudaGetSymbolAddress((void**)&pB, g_bufB);

    dim3 cgrid(TLEN / TILE_T, CH / TILE_CO, BATCH);   // (4, 5, 256)
    const int sgrid = (NSUBJ * CH + 255) / 256;
    const size_t n4 = (size_t)BATCH * CH * TLEN / 4;
    const int tgrid = (int)((n4 + 255) / 256);

    count_kernel<<<1, BATCH>>>(subj);

    // Layer 0: conv0(X) -> Y0(bufA); stats; G0 = gelu(bn(Y0)) in place.
    transpose_w_kernel<<<(CH * CIN0 * 3 + 255) / 256, 256>>>(w0, CIN0);
    zero_stats_kernel<<<sgrid, 256>>>();
    conv_kernel<CIN0, false><<<cgrid, NTH>>>(X, b0, subj, pA);
    finalize_kernel<<<sgrid, 256>>>(g0, be0);
    bn_gelu_kernel<<<tgrid, 256>>>(pA, pA, subj);

    // Layer 1: Y1 = conv1(G0) + G0 -> bufB; stats; G1 in place.
    transpose_w_kernel<<<(CH * CH * 3 + 255) / 256, 256>>>(w1, CH);
    zero_stats_kernel<<<sgrid, 256>>>();
    conv_kernel<CH, true><<<cgrid, NTH>>>(pA, b1, subj, pB);
    finalize_kernel<<<sgrid, 256>>>(g1, be1);
    bn_gelu_kernel<<<tgrid, 256>>>(pB, pB, subj);

    // Layer 2: Y2 = conv2(G1) + G1 -> bufA; stats; final gelu(bn) -> d_out.
    transpose_w_kernel<<<(CH * CH * 3 + 255) / 256, 256>>>(w2, CH);
    zero_stats_kernel<<<sgrid, 256>>>();
    conv_kernel<CH, true><<<cgrid, NTH>>>(pB, b2, subj, pA);
    finalize_kernel<<<sgrid, 256>>>(g2, be2);
    bn_gelu_kernel<<<tgrid, 256>>>(pA, out, subj);
}

// round 4
// speedup vs baseline: 3.1570x; 3.1570x over previous
#include <cuda_runtime.h>
#include <math.h>
#include <stdint.h>

#define BATCH 256
#define TLEN  512
#define CIN0  271
#define CH    320
#define NSUBJ 4
#define EPSV  1e-5f
#define PADROWS 516

// ---------------- scratch (__device__ globals; no allocs allowed) ----------
__device__ __align__(16) float g_bufA[(size_t)BATCH * PADROWS * CH];
__device__ __align__(16) float g_bufB[(size_t)BATCH * PADROWS * CH];
__device__ __align__(16) float g_w[CH * 960];   // [co][KPAD] tf32-rounded, padded
__device__ float g_sum[NSUBJ * CH];
__device__ float g_sumsq[NSUBJ * CH];
__device__ float g_scale[NSUBJ * CH];
__device__ float g_shift[NSUBJ * CH];
__device__ int   g_cnt[NSUBJ];

// ---------------- helpers ---------------------------------------------------
__device__ __forceinline__ uint32_t smem_u32(const void* p) {
    uint32_t a;
    asm("{ .reg .u64 t; cvta.to.shared.u64 t, %1; cvt.u32.u64 %0, t; }"
        : "=r"(a) : "l"(p));
    return a;
}
__device__ __forceinline__ void cpasync16(uint32_t s, const void* g) {
    asm volatile("cp.async.cg.shared.global [%0], [%1], 16;" :: "r"(s), "l"(g));
}
#define CP_COMMIT() asm volatile("cp.async.commit_group;" ::: "memory")
#define CP_WAIT1()  asm volatile("cp.async.wait_group 1;" ::: "memory")

__device__ __forceinline__ void mma_tf32(float* d, const uint32_t* a,
                                         uint32_t b0, uint32_t b1) {
    asm volatile(
        "mma.sync.aligned.m16n8k8.row.col.f32.tf32.tf32.f32 "
        "{%0,%1,%2,%3}, {%4,%5,%6,%7}, {%8,%9}, {%0,%1,%2,%3};"
        : "+f"(d[0]), "+f"(d[1]), "+f"(d[2]), "+f"(d[3])
        : "r"(a[0]), "r"(a[1]), "r"(a[2]), "r"(a[3]), "r"(b0), "r"(b1));
}
__device__ __forceinline__ float to_tf32(float x) {
    float r; asm("cvt.rna.tf32.f32 %0, %1;" : "=f"(r) : "f"(x)); return r;
}
__device__ __forceinline__ float gelu_f(float x) {
    return 0.5f * x * (1.0f + erff(x * 0.7071067811865475f));
}

// ------------------------- small kernels -----------------------------------
__global__ void cb_count(const int* __restrict__ subj) {
    __shared__ int c[NSUBJ];
    int tid = threadIdx.x;
    if (tid < NSUBJ) c[tid] = 0;
    __syncthreads();
    atomicAdd(&c[subj[tid]], 1);
    __syncthreads();
    if (tid < NSUBJ) g_cnt[tid] = c[tid];
}
__global__ void cb_zero_stats() {
    int i = blockIdx.x * blockDim.x + threadIdx.x;
    if (i < NSUBJ * CH) { g_sum[i] = 0.f; g_sumsq[i] = 0.f; }
}
// weights [co][cin][3] -> g_w[co][tap*cpad + ci], tf32-rounded, zero-padded
__global__ void cb_tw(const float* __restrict__ w, int cin, int cpad, int kpad) {
    int i = blockIdx.x * blockDim.x + threadIdx.x;
    int n = CH * kpad;
    if (i >= n) return;
    int k  = i % kpad;
    int co = i / kpad;
    int tap = k / cpad, ci = k % cpad;
    float v = 0.f;
    if (tap < 3 && ci < cin) v = w[((size_t)co * cin + ci) * 3 + tap];
    g_w[i] = to_tf32(v);
}
// X [b][ci][t] -> bufA padded NTC [b][t+1][272] (col 271 zero), tf32-rounded
__global__ void cb_xT(const float* __restrict__ X, float* __restrict__ dst) {
    __shared__ float tile[32][33];
    int lx = threadIdx.x, ly = threadIdx.y;
    int t0 = blockIdx.x * 32, c0 = blockIdx.y * 32, b = blockIdx.z;
#pragma unroll
    for (int i = 0; i < 4; i++) {
        int ci = c0 + ly + i * 8;
        float v = (ci < CIN0) ? X[((size_t)b * CIN0 + ci) * TLEN + t0 + lx] : 0.f;
        tile[ly + i * 8][lx] = to_tf32(v);
    }
    __syncthreads();
#pragma unroll
    for (int i = 0; i < 4; i++) {
        int tr = ly + i * 8;
        int ci = c0 + lx;
        if (ci < 272)
            dst[((size_t)b * PADROWS + t0 + tr + 1) * 272 + ci] = tile[lx][tr];
    }
}
// zero pad rows {0,513,514,515} of a padded NTC buffer of row-width W
__global__ void cb_zero_pads(float* __restrict__ buf, int W) {
    int i = blockIdx.x * blockDim.x + threadIdx.x;
    int n = BATCH * 4 * W;
    if (i >= n) return;
    int c = i % W;
    int rr = (i / W) & 3;
    int b = i / (4 * W);
    int row = (rr == 0) ? 0 : (512 + rr);
    buf[((size_t)b * PADROWS + row) * W + c] = 0.f;
}
__global__ void cb_finalize(const float* __restrict__ gamma,
                            const float* __restrict__ beta) {
    int i = blockIdx.x * blockDim.x + threadIdx.x;
    if (i >= NSUBJ * CH) return;
    int s = i / CH;
    float cnt  = fmaxf((float)g_cnt[s] * (float)TLEN, 1.0f);
    float mean = g_sum[i] / cnt;
    float var  = g_sumsq[i] / cnt - mean * mean;
    float sc   = gamma[i] * rsqrtf(var + EPSV);
    g_scale[i] = sc;
    g_shift[i] = beta[i] - mean * sc;
}
// in-place BN+GELU (tf32-rounded output) on padded NTC buffer rows 1..512
__global__ void cb_bn_gelu(float* __restrict__ buf, const int* __restrict__ subj) {
    int i = blockIdx.x * blockDim.x + threadIdx.x;
    const int NB = 512 * (CH / 4);
    if (i >= BATCH * NB) return;
    int b = i / NB;
    int rem = i - b * NB;
    int r = rem / (CH / 4);
    int c4 = rem - r * (CH / 4);
    int s = subj[b];
    float4 sc = ((const float4*)g_scale)[s * (CH / 4) + c4];
    float4 sh = ((const float4*)g_shift)[s * (CH / 4) + c4];
    float4* p = (float4*)buf + ((size_t)b * PADROWS + r + 1) * (CH / 4) + c4;
    float4 v = *p;
    v.x = to_tf32(gelu_f(fmaf(v.x, sc.x, sh.x)));
    v.y = to_tf32(gelu_f(fmaf(v.y, sc.y, sh.y)));
    v.z = to_tf32(gelu_f(fmaf(v.z, sc.z, sh.z)));
    v.w = to_tf32(gelu_f(fmaf(v.w, sc.w, sh.w)));
    *p = v;
}
// final: BN+GELU (full precision) + NTC->NCT transpose into d_out
__global__ void cb_out(const float* __restrict__ buf, const int* __restrict__ subj,
                       float* __restrict__ out) {
    __shared__ float tile[32][33];
    int lx = threadIdx.x, ly = threadIdx.y;
    int t0 = blockIdx.x * 32, c0 = blockIdx.y * 32, b = blockIdx.z;
    int s = subj[b];
    float sc = g_scale[s * CH + c0 + lx];
    float sh = g_shift[s * CH + c0 + lx];
#pragma unroll
    for (int i = 0; i < 4; i++) {
        int tr = ly + i * 8;
        float v = buf[((size_t)b * PADROWS + t0 + tr + 1) * CH + c0 + lx];
        tile[tr][lx] = gelu_f(fmaf(v, sc, sh));
    }
    __syncthreads();
#pragma unroll
    for (int i = 0; i < 4; i++) {
        int cr = ly + i * 8;
        out[((size_t)b * CH + c0 + cr) * TLEN + t0 + lx] = tile[lx][cr];
    }
}

// ------------------------- conv GEMM via mma.sync tf32 ---------------------
// A: padded NTC (row stride CSTRIDE), pre-tf32-rounded. B: g_w [CH][KPAD].
// Block: 128 t-rows x 160 co. grid = (4 t, 2 co, 256 b). 256 threads.
// Warp grid 4m x 2n -> warp tile 32 x 80. Fragments per PTX m16n8k8 layout.
#define CONV_SMEM ((2 * 128 * 36 + 2 * 160 * 36) * 4)
template <int KPAD, int CSTRIDE, bool RES>
__global__ void __launch_bounds__(256) cb_conv(
    const float* __restrict__ in, const float* __restrict__ wts,
    const float* __restrict__ bias, const int* __restrict__ subj,
    float* __restrict__ out)
{
    extern __shared__ float sm[];
    float* As = sm;               // [2][128][36]
    float* Bs = sm + 2 * 128 * 36; // [2][160][36]
    const uint32_t aB = smem_u32(As);
    const uint32_t bB = smem_u32(Bs);

    const int tid = threadIdx.x;
    const int wid = tid >> 5, lane = tid & 31;
    const int g = lane >> 2, tig = lane & 3;
    const int wm = wid & 3, wn = wid >> 2;
    const int b = blockIdx.z, coBase = blockIdx.y * 160, tBlk = blockIdx.x * 128;
    constexpr int NC = KPAD / 32;

    const float* Ag = in + ((size_t)b * PADROWS + tBlk) * CSTRIDE;
    const float* Wg = wts + (size_t)coBase * KPAD;

    // async-copy one 32-k chunk into buffer (c & 1)
    auto issue = [&](int c) {
        const uint32_t ao = aB + (c & 1) * (128 * 36 * 4);
        const uint32_t bo = bB + (c & 1) * (160 * 36 * 4);
#pragma unroll
        for (int it = 0; it < 4; it++) {
            int idx = tid + it * 256;
            int row = idx >> 3, j = idx & 7;
            cpasync16(ao + row * 144 + j * 16,
                      Ag + (size_t)row * CSTRIDE + c * 32 + j * 4);
        }
#pragma unroll
        for (int it = 0; it < 5; it++) {
            int idx = tid + it * 256;
            int row = idx >> 3, j = idx & 7;
            cpasync16(bo + row * 144 + j * 16,
                      Wg + (size_t)row * KPAD + c * 32 + j * 4);
        }
    };

    float acc[2][10][4];
#pragma unroll
    for (int mf = 0; mf < 2; mf++)
#pragma unroll
        for (int nf = 0; nf < 10; nf++)
#pragma unroll
            for (int j = 0; j < 4; j++) acc[mf][nf][j] = 0.f;

    issue(0); CP_COMMIT();
    for (int c = 0; c < NC; c++) {
        if (c + 1 < NC) issue(c + 1);
        CP_COMMIT();
        CP_WAIT1();
        __syncthreads();
        const float* A = As + (c & 1) * (128 * 36);
        const float* B = Bs + (c & 1) * (160 * 36);
#pragma unroll
        for (int ks = 0; ks < 4; ks++) {
            const int k0 = ks * 8;
            uint32_t af[2][4];
#pragma unroll
            for (int mf = 0; mf < 2; mf++) {
                int r = wm * 32 + mf * 16 + g;
                af[mf][0] = __float_as_uint(A[r * 36 + k0 + tig]);
                af[mf][1] = __float_as_uint(A[(r + 8) * 36 + k0 + tig]);
                af[mf][2] = __float_as_uint(A[r * 36 + k0 + tig + 4]);
                af[mf][3] = __float_as_uint(A[(r + 8) * 36 + k0 + tig + 4]);
            }
#pragma unroll
            for (int nf = 0; nf < 10; nf++) {
                int n = wn * 80 + nf * 8 + g;
                uint32_t b0 = __float_as_uint(B[n * 36 + k0 + tig]);
                uint32_t b1 = __float_as_uint(B[n * 36 + k0 + tig + 4]);
                mma_tf32(acc[0][nf], af[0], b0, b1);
                mma_tf32(acc[1][nf], af[1], b0, b1);
            }
        }
        __syncthreads();
    }

    // Epilogue: bias (+res), store NTC, fused per-subject stats.
    const int sbj = subj[b];
#pragma unroll
    for (int nf = 0; nf < 10; nf++) {
        const int co = coBase + wn * 80 + nf * 8 + 2 * tig;
        const float bv0 = __ldg(bias + co), bv1 = __ldg(bias + co + 1);
        float s0 = 0.f, s1 = 0.f, q0 = 0.f, q1 = 0.f;
#pragma unroll
        for (int mf = 0; mf < 2; mf++) {
            const int trow = tBlk + wm * 32 + mf * 16 + g + 1;
            float y0 = acc[mf][nf][0] + bv0, y1 = acc[mf][nf][1] + bv1;
            float y2 = acc[mf][nf][2] + bv0, y3 = acc[mf][nf][3] + bv1;
            if (RES) {
                float2 r0 = *(const float2*)(in + ((size_t)b * PADROWS + trow) * CSTRIDE + co);
                float2 r1 = *(const float2*)(in + ((size_t)b * PADROWS + trow + 8) * CSTRIDE + co);
                y0 += r0.x; y1 += r0.y; y2 += r1.x; y3 += r1.y;
            }
            *(float2*)(out + ((size_t)b * PADROWS + trow) * CH + co) = make_float2(y0, y1);
            *(float2*)(out + ((size_t)b * PADROWS + trow + 8) * CH + co) = make_float2(y2, y3);
            s0 += y0 + y2; s1 += y1 + y3;
            q0 += y0 * y0 + y2 * y2; q1 += y1 * y1 + y3 * y3;
        }
#pragma unroll
        for (int off = 16; off >= 4; off >>= 1) {
            s0 += __shfl_down_sync(0xffffffffu, s0, off);
            s1 += __shfl_down_sync(0xffffffffu, s1, off);
            q0 += __shfl_down_sync(0xffffffffu, q0, off);
            q1 += __shfl_down_sync(0xffffffffu, q1, off);
        }
        if (lane < 4) {
            atomicAdd(&g_sum[sbj * CH + co], s0);
            atomicAdd(&g_sum[sbj * CH + co + 1], s1);
            atomicAdd(&g_sumsq[sbj * CH + co], q0);
            atomicAdd(&g_sumsq[sbj * CH + co + 1], q1);
        }
    }
}

// ---------------------------------------------------------------------------
extern "C" void kernel_launch(void* const* d_in, const int* in_sizes, int n_in,
                              void* d_out, int out_size) {
    const float* X    = (const float*)d_in[0];
    const int*   subj = (const int*)  d_in[1];
    const float* w0   = (const float*)d_in[2];
    const float* b0   = (const float*)d_in[3];
    const float* w1   = (const float*)d_in[4];
    const float* b1   = (const float*)d_in[5];
    const float* w2   = (const float*)d_in[6];
    const float* b2   = (const float*)d_in[7];
    const float* g0   = (const float*)d_in[8];
    const float* be0  = (const float*)d_in[9];
    const float* g1   = (const float*)d_in[10];
    const float* be1  = (const float*)d_in[11];
    const float* g2   = (const float*)d_in[12];
    const float* be2  = (const float*)d_in[13];
    float* out = (float*)d_out;
    (void)in_sizes; (void)n_in; (void)out_size;

    float *pA, *pB, *pW;
    cudaGetSymbolAddress((void**)&pA, g_bufA);
    cudaGetSymbolAddress((void**)&pB, g_bufB);
    cudaGetSymbolAddress((void**)&pW, g_w);

    cudaFuncSetAttribute((const void*)cb_conv<832, 272, false>,
                         cudaFuncAttributeMaxDynamicSharedMemorySize, CONV_SMEM);
    cudaFuncSetAttribute((const void*)cb_conv<960, 320, true>,
                         cudaFuncAttributeMaxDynamicSharedMemorySize, CONV_SMEM);

    const int sgrid = (NSUBJ * CH + 255) / 256;
    const dim3 cgrid(4, 2, BATCH);
    const int bngrid = (BATCH * 512 * (CH / 4) + 255) / 256;

    cb_count<<<1, BATCH>>>(subj);

    // ---- layer 0: conv0(Xt) -> bufB; bn+gelu in place ----
    cb_tw<<<(CH * 832 + 255) / 256, 256>>>(w0, CIN0, 272, 832);
    cb_xT<<<dim3(16, 9, BATCH), dim3(32, 8)>>>(X, pA);
    cb_zero_pads<<<(BATCH * 4 * 272 + 255) / 256, 256>>>(pA, 272);
    cb_zero_stats<<<sgrid, 256>>>();
    cb_conv<832, 272, false><<<cgrid, 256, CONV_SMEM>>>(pA, pW, b0, subj, pB);
    cb_finalize<<<sgrid, 256>>>(g0, be0);
    cb_bn_gelu<<<bngrid, 256>>>(pB, subj);

    // ---- layer 1: conv1(bufB)+res -> bufA; bn+gelu in place ----
    cb_tw<<<(CH * 960 + 255) / 256, 256>>>(w1, CH, CH, 960);
    cb_zero_pads<<<(BATCH * 4 * CH + 255) / 256, 256>>>(pB, CH);
    cb_zero_stats<<<sgrid, 256>>>();
    cb_conv<960, 320, true><<<cgrid, 256, CONV_SMEM>>>(pB, pW, b1, subj, pA);
    cb_finalize<<<sgrid, 256>>>(g1, be1);
    cb_bn_gelu<<<bngrid, 256>>>(pA, subj);

    // ---- layer 2: conv2(bufA)+res -> bufB; bn+gelu+transpose -> out ----
    cb_tw<<<(CH * 960 + 255) / 256, 256>>>(w2, CH, CH, 960);
    cb_zero_pads<<<(BATCH * 4 * CH + 255) / 256, 256>>>(pA, CH);
    cb_zero_stats<<<sgrid, 256>>>();
    cb_conv<960, 320, true><<<cgrid, 256, CONV_SMEM>>>(pA, pW, b2, subj, pB);
    cb_finalize<<<sgrid, 256>>>(g2, be2);
    cb_out<<<dim3(16, 10, BATCH), dim3(32, 8)>>>(pB, subj, out);
}